// round 1
// baseline (speedup 1.0000x reference)
#include <cuda_runtime.h>

#define NN   100000
#define EE   3200000
#define DDIM 256
#define D4   64          // DDIM/4
#define KK   1024
#define BM   64          // rows per block in hopfield
#define TKT  64          // K tile
#define ALPHA_C  0.5f
#define LAMBDA_C 0.1f
#define EPS_C    1e-5f

// ---------------- scratch (device globals; no allocation allowed) ----------------
__device__ float g_x[(size_t)NN * DDIM];     // x after iteration 1
__device__ float g_ret[(size_t)NN * DDIM];   // hopfield retrieved
__device__ float g_agg[(size_t)NN * DDIM];   // laplacian scatter accumulator
__device__ float g_deg[NN];
__device__ float g_dinv[NN];
__device__ int   g_rowi[EE];
__device__ int   g_coli[EE];
__device__ int   g_is64;

// ---------------- dtype detection for edge_index (int32 vs int64) ----------------
__global__ void detect_kernel(const long long* __restrict__ e64) {
    if (threadIdx.x == 0) {
        int is64 = 1;
        #pragma unroll 1
        for (int i = 0; i < 64; i++) {
            long long v = e64[i];
            if (v < 0 || v >= (long long)NN) { is64 = 0; break; }
        }
        g_is64 = is64;
    }
}

__global__ void zero_deg_kernel() {
    int i = blockIdx.x * blockDim.x + threadIdx.x;
    if (i < NN) g_deg[i] = 0.0f;
}

__global__ void zero_agg_kernel() {
    int i = blockIdx.x * blockDim.x + threadIdx.x;
    if (i < NN * D4) {
        ((float4*)g_agg)[i] = make_float4(0.f, 0.f, 0.f, 0.f);
    }
}

// convert edges to int32 row/col arrays and accumulate degree (over col)
__global__ void convert_deg_kernel(const void* __restrict__ eidx) {
    int e = blockIdx.x * blockDim.x + threadIdx.x;
    if (e >= EE) return;
    int r, c;
    if (g_is64) {
        const long long* p = (const long long*)eidx;
        r = (int)p[e];
        c = (int)p[(size_t)EE + e];
    } else {
        const int* p = (const int*)eidx;
        r = p[e];
        c = p[EE + e];
    }
    g_rowi[e] = r;
    g_coli[e] = c;
    atomicAdd(&g_deg[c], 1.0f);
}

__global__ void dinv_kernel() {
    int n = blockIdx.x * blockDim.x + threadIdx.x;
    if (n >= NN) return;
    float d = g_deg[n];
    g_dinv[n] = (d > 0.0f) ? rsqrtf(fmaxf(d, 1.0f)) : 0.0f;
}

// ---------------- fused Hopfield: softmax(x M^T) M ----------------
// grid: ceil(N/BM) blocks x 256 threads. Dynamic smem ~150 KB.
// smem layout: xs[BM][65] float4 | ms[TKT][65] float4 | es[BM][65] float | den[BM]
__global__ __launch_bounds__(256, 1)
void hopfield_kernel(const float4* __restrict__ x4,
                     const float4* __restrict__ m4,
                     float4* __restrict__ ret4) {
    extern __shared__ float smem_raw[];
    float4* xs = (float4*)smem_raw;           // BM * 65
    float4* ms = xs + BM * 65;                // TKT * 65
    float*  es = (float*)(ms + TKT * 65);     // BM * 65
    float*  den = es + BM * 65;               // BM

    const int tid  = threadIdx.x;
    const int row0 = blockIdx.x * BM;

    // load x tile (zero-pad past N)
    for (int t = tid; t < BM * D4; t += 256) {
        int r = t >> 6, c = t & 63;
        float4 v = make_float4(0.f, 0.f, 0.f, 0.f);
        if (row0 + r < NN) v = x4[(size_t)(row0 + r) * D4 + c];
        xs[r * 65 + c] = v;
    }
    if (tid < BM) den[tid] = 0.0f;
    __syncthreads();

    const int tr = tid & 15;   // row group (rows tr + 16a)
    const int tc = tid >> 4;   // col group (ks / d-cols tc + 16b)

    float4 acc[4][4];
    #pragma unroll
    for (int a = 0; a < 4; a++)
        #pragma unroll
        for (int b = 0; b < 4; b++)
            acc[a][b] = make_float4(0.f, 0.f, 0.f, 0.f);

    for (int kt = 0; kt < KK / TKT; kt++) {
        // load M tile
        for (int t = tid; t < TKT * D4; t += 256) {
            int k = t >> 6, c = t & 63;
            ms[k * 65 + c] = m4[(size_t)(kt * TKT + k) * D4 + c];
        }
        __syncthreads();

        // ---- logits: s[a][b] = dot(x[row], m[k]) ----
        float s[4][4];
        #pragma unroll
        for (int a = 0; a < 4; a++)
            #pragma unroll
            for (int b = 0; b < 4; b++) s[a][b] = 0.f;

        #pragma unroll 2
        for (int i = 0; i < D4; i++) {
            float4 xv[4], mv[4];
            #pragma unroll
            for (int a = 0; a < 4; a++) xv[a] = xs[(tr + 16 * a) * 65 + i];
            #pragma unroll
            for (int b = 0; b < 4; b++) mv[b] = ms[(tc + 16 * b) * 65 + i];
            #pragma unroll
            for (int a = 0; a < 4; a++)
                #pragma unroll
                for (int b = 0; b < 4; b++)
                    s[a][b] += xv[a].x * mv[b].x + xv[a].y * mv[b].y +
                               xv[a].z * mv[b].z + xv[a].w * mv[b].w;
        }

        // exp + store + denominator
        #pragma unroll
        for (int a = 0; a < 4; a++) {
            float psum = 0.f;
            #pragma unroll
            for (int b = 0; b < 4; b++) {
                float e = __expf(s[a][b]);
                es[(tr + 16 * a) * 65 + (tc + 16 * b)] = e;
                psum += e;
            }
            atomicAdd(&den[tr + 16 * a], psum);
        }
        __syncthreads();

        // ---- accumulate: acc[row][d] += e[row][k] * m[k][d] ----
        #pragma unroll 2
        for (int k = 0; k < TKT; k++) {
            float ev[4];
            #pragma unroll
            for (int a = 0; a < 4; a++) ev[a] = es[(tr + 16 * a) * 65 + k];
            float4 mv[4];
            #pragma unroll
            for (int b = 0; b < 4; b++) mv[b] = ms[k * 65 + (tc + 16 * b)];
            #pragma unroll
            for (int a = 0; a < 4; a++)
                #pragma unroll
                for (int b = 0; b < 4; b++) {
                    acc[a][b].x += ev[a] * mv[b].x;
                    acc[a][b].y += ev[a] * mv[b].y;
                    acc[a][b].z += ev[a] * mv[b].z;
                    acc[a][b].w += ev[a] * mv[b].w;
                }
        }
        __syncthreads();
    }

    // write retrieved = acc / den
    #pragma unroll
    for (int a = 0; a < 4; a++) {
        int r = row0 + tr + 16 * a;
        if (r < NN) {
            float inv = 1.0f / den[tr + 16 * a];
            #pragma unroll
            for (int b = 0; b < 4; b++) {
                float4 v = acc[a][b];
                v.x *= inv; v.y *= inv; v.z *= inv; v.w *= inv;
                ret4[(size_t)r * D4 + (tc + 16 * b)] = v;
            }
        }
    }
}

// ---------------- Laplacian scatter: agg[row] += dinv[col] * x[col] ----------------
// one warp per edge; vector reductions (red.global.v4.f32.add, sm_90+)
__global__ __launch_bounds__(256)
void scatter_kernel(const float4* __restrict__ x4) {
    int gtid = blockIdx.x * blockDim.x + threadIdx.x;
    int warp = gtid >> 5;
    int lane = threadIdx.x & 31;
    if (warp >= EE) return;
    int r = g_rowi[warp];
    int c = g_coli[warp];
    float s = g_dinv[c];
    const float4* src = x4 + (size_t)c * D4;
    float4* dst = ((float4*)g_agg) + (size_t)r * D4;
    #pragma unroll
    for (int j = 0; j < 2; j++) {
        int idx = lane + 32 * j;
        float4 v = src[idx];
        v.x *= s; v.y *= s; v.z *= s; v.w *= s;
        asm volatile("red.global.v4.f32.add [%0], {%1, %2, %3, %4};"
                     :: "l"(dst + idx), "f"(v.x), "f"(v.y), "f"(v.z), "f"(v.w)
                     : "memory");
    }
}

// ---------------- combine + layernorm ----------------
// x_new = (1-a)x + a*(ret - 2*lambda*(x - dinv*agg)); then LN
// one warp per node
__global__ __launch_bounds__(256)
void combine_ln_kernel(const float4* __restrict__ xin4,
                       const float4* __restrict__ gamma4,
                       const float4* __restrict__ beta4,
                       float4* __restrict__ out4) {
    int gtid = blockIdx.x * blockDim.x + threadIdx.x;
    int node = gtid >> 5;
    int lane = threadIdx.x & 31;
    if (node >= NN) return;

    const float lc = 2.0f * LAMBDA_C;                 // 0.2
    const float cx = (1.0f - ALPHA_C) - ALPHA_C * lc; // 0.4
    const float cr = ALPHA_C;                         // 0.5
    const float ca = ALPHA_C * lc;                    // 0.1 (times dinv)

    size_t base = (size_t)node * D4;
    float s = g_dinv[node] * ca;
    const float4* rp = ((const float4*)g_ret) + base;
    const float4* ap = ((const float4*)g_agg) + base;

    float4 h[2];
    float sum = 0.f, sumsq = 0.f;
    #pragma unroll
    for (int j = 0; j < 2; j++) {
        int idx = lane + 32 * j;
        float4 xv = xin4[base + idx];
        float4 rv = rp[idx];
        float4 av = ap[idx];
        float4 hv;
        hv.x = cx * xv.x + cr * rv.x + s * av.x;
        hv.y = cx * xv.y + cr * rv.y + s * av.y;
        hv.z = cx * xv.z + cr * rv.z + s * av.z;
        hv.w = cx * xv.w + cr * rv.w + s * av.w;
        h[j] = hv;
        sum   += hv.x + hv.y + hv.z + hv.w;
        sumsq += hv.x * hv.x + hv.y * hv.y + hv.z * hv.z + hv.w * hv.w;
    }
    #pragma unroll
    for (int o = 16; o > 0; o >>= 1) {
        sum   += __shfl_xor_sync(0xffffffffu, sum, o);
        sumsq += __shfl_xor_sync(0xffffffffu, sumsq, o);
    }
    const float invD = 1.0f / (float)DDIM;
    float mu  = sum * invD;
    float var = sumsq * invD - mu * mu;
    float rs  = rsqrtf(var + EPS_C);

    #pragma unroll
    for (int j = 0; j < 2; j++) {
        int idx = lane + 32 * j;
        float4 gv = gamma4[idx];
        float4 bv = beta4[idx];
        float4 hv = h[j];
        float4 ov;
        ov.x = (hv.x - mu) * rs * gv.x + bv.x;
        ov.y = (hv.y - mu) * rs * gv.y + bv.y;
        ov.z = (hv.z - mu) * rs * gv.z + bv.z;
        ov.w = (hv.w - mu) * rs * gv.w + bv.w;
        out4[base + idx] = ov;
    }
}

// ---------------- launch ----------------
extern "C" void kernel_launch(void* const* d_in, const int* in_sizes, int n_in,
                              void* d_out, int out_size) {
    const float* x     = (const float*)d_in[0];
    const void*  eidx  = d_in[1];
    const float* mem   = (const float*)d_in[2];
    const float* gamma = (const float*)d_in[3];
    const float* beta  = (const float*)d_in[4];
    float* out = (float*)d_out;

    const int SMEM_BYTES = (BM * 65 + TKT * 65) * 16 + BM * 65 * 4 + BM * 4;
    cudaFuncSetAttribute(hopfield_kernel,
                         cudaFuncAttributeMaxDynamicSharedMemorySize, SMEM_BYTES);

    void *p_x = nullptr;
    cudaGetSymbolAddress(&p_x, g_x);
    void *p_ret = nullptr;
    cudaGetSymbolAddress(&p_ret, g_ret);

    // graph preprocessing (must be recomputed every call — deterministic)
    detect_kernel<<<1, 32>>>((const long long*)eidx);
    zero_deg_kernel<<<(NN + 255) / 256, 256>>>();
    convert_deg_kernel<<<(EE + 255) / 256, 256>>>(eidx);
    dinv_kernel<<<(NN + 255) / 256, 256>>>();

    const float* xin = x;
    for (int it = 0; it < 2; it++) {
        float* xout = (it == 0) ? (float*)p_x : out;

        zero_agg_kernel<<<(NN * D4 + 255) / 256, 256>>>();
        hopfield_kernel<<<(NN + BM - 1) / BM, 256, SMEM_BYTES>>>(
            (const float4*)xin, (const float4*)mem, (float4*)p_ret);
        scatter_kernel<<<(EE * 32 + 255) / 256, 256>>>((const float4*)xin);
        combine_ln_kernel<<<(NN * 32 + 255) / 256, 256>>>(
            (const float4*)xin, (const float4*)gamma, (const float4*)beta,
            (float4*)xout);

        xin = xout;
    }
}

// round 2
// speedup vs baseline: 2.8197x; 2.8197x over previous
#include <cuda_runtime.h>
#include <cstdint>

#define NN   100000
#define EE   3200000
#define DDIM 256
#define D4   64
#define KK   1024
#define ALPHA_C  0.5f
#define LAMBDA_C 0.1f
#define EPS_C    1e-5f

// hopfield mma tiling
#define BM   64      // rows per block
#define BK   128     // K (memory slots) tile
// smem strides in halves (bf16)
#define XS_STRIDE 264
#define MS_STRIDE 264
#define PS_STRIDE 136
#define XS_OFF 0
#define MS_OFF (BM * XS_STRIDE)                    // 16896
#define PS_OFF (MS_OFF + BK * MS_STRIDE)           // 50688
#define DEN_BYTE_OFF ((PS_OFF + BM * PS_STRIDE) * 2)   // 118784
#define SMEM_BYTES (DEN_BYTE_OFF + BM * 4)             // 119040

// ---------------- scratch (device globals; no allocation allowed) ----------------
__device__ float g_x[(size_t)NN * DDIM];
__device__ float g_ret[(size_t)NN * DDIM];
__device__ float g_agg[(size_t)NN * DDIM];
__device__ float g_deg[NN];
__device__ float g_dinv[NN];
__device__ int   g_rowi[EE];
__device__ int   g_coli[EE];
__device__ int   g_is64;
__device__ __align__(16) unsigned short g_xbf[(size_t)NN * DDIM];   // bf16 x
__device__ __align__(16) unsigned short g_mbf[(size_t)KK * DDIM];   // bf16 memory

// ---------------- dtype detection for edge_index (int32 vs int64) ----------------
__global__ void detect_kernel(const long long* __restrict__ e64) {
    if (threadIdx.x == 0) {
        int is64 = 1;
        #pragma unroll 1
        for (int i = 0; i < 64; i++) {
            long long v = e64[i];
            if (v < 0 || v >= (long long)NN) { is64 = 0; break; }
        }
        g_is64 = is64;
    }
}

__global__ void zero_deg_kernel() {
    int i = blockIdx.x * blockDim.x + threadIdx.x;
    if (i < NN) g_deg[i] = 0.0f;
}

__global__ void zero_agg_kernel() {
    int i = blockIdx.x * blockDim.x + threadIdx.x;
    if (i < NN * D4) ((float4*)g_agg)[i] = make_float4(0.f, 0.f, 0.f, 0.f);
}

__global__ void convert_deg_kernel(const void* __restrict__ eidx) {
    int e = blockIdx.x * blockDim.x + threadIdx.x;
    if (e >= EE) return;
    int r, c;
    if (g_is64) {
        const long long* p = (const long long*)eidx;
        r = (int)p[e];
        c = (int)p[(size_t)EE + e];
    } else {
        const int* p = (const int*)eidx;
        r = p[e];
        c = p[EE + e];
    }
    g_rowi[e] = r;
    g_coli[e] = c;
    atomicAdd(&g_deg[c], 1.0f);
}

__global__ void dinv_kernel() {
    int n = blockIdx.x * blockDim.x + threadIdx.x;
    if (n >= NN) return;
    float d = g_deg[n];
    g_dinv[n] = (d > 0.0f) ? rsqrtf(fmaxf(d, 1.0f)) : 0.0f;
}

// fp32 -> bf16 convert (8 floats per thread)
__global__ void conv_bf16_kernel(const float4* __restrict__ src,
                                 uint4* __restrict__ dst, int n16) {
    int i = blockIdx.x * blockDim.x + threadIdx.x;
    if (i >= n16) return;
    float4 a = src[2 * i], b = src[2 * i + 1];
    uint4 o;
    asm("cvt.rn.bf16x2.f32 %0, %1, %2;" : "=r"(o.x) : "f"(a.y), "f"(a.x));
    asm("cvt.rn.bf16x2.f32 %0, %1, %2;" : "=r"(o.y) : "f"(a.w), "f"(a.z));
    asm("cvt.rn.bf16x2.f32 %0, %1, %2;" : "=r"(o.z) : "f"(b.y), "f"(b.x));
    asm("cvt.rn.bf16x2.f32 %0, %1, %2;" : "=r"(o.w) : "f"(b.w), "f"(b.z));
    dst[i] = o;
}

// ---------------- mma helpers ----------------
__device__ __forceinline__ void ldsm_x4(uint32_t (&r)[4], uint32_t addr) {
    asm volatile("ldmatrix.sync.aligned.m8n8.x4.shared.b16 {%0,%1,%2,%3}, [%4];"
        : "=r"(r[0]), "=r"(r[1]), "=r"(r[2]), "=r"(r[3]) : "r"(addr));
}
__device__ __forceinline__ void ldsm_x4_t(uint32_t (&r)[4], uint32_t addr) {
    asm volatile("ldmatrix.sync.aligned.m8n8.x4.trans.shared.b16 {%0,%1,%2,%3}, [%4];"
        : "=r"(r[0]), "=r"(r[1]), "=r"(r[2]), "=r"(r[3]) : "r"(addr));
}
__device__ __forceinline__ void mma_bf16(float (&d)[4], const uint32_t (&a)[4],
                                         uint32_t b0, uint32_t b1) {
    asm volatile("mma.sync.aligned.m16n8k16.row.col.f32.bf16.bf16.f32 "
        "{%0,%1,%2,%3}, {%4,%5,%6,%7}, {%8,%9}, {%0,%1,%2,%3};"
        : "+f"(d[0]), "+f"(d[1]), "+f"(d[2]), "+f"(d[3])
        : "r"(a[0]), "r"(a[1]), "r"(a[2]), "r"(a[3]), "r"(b0), "r"(b1));
}

// ---------------- fused Hopfield via tensor cores ----------------
// grid: ceil(N/BM) x 256 threads (8 warps: mw = w>>2 in {0,1}, nw = w&3)
__global__ __launch_bounds__(256, 1)
void hopfield_mma_kernel(const uint4* __restrict__ xbf,
                         const uint4* __restrict__ mbf,
                         float2* __restrict__ ret2) {
    extern __shared__ char smem[];
    unsigned short* sh = (unsigned short*)smem;
    float* den = (float*)(smem + DEN_BYTE_OFF);
    uint32_t sbase = (uint32_t)__cvta_generic_to_shared(smem);

    const int tid  = threadIdx.x;
    const int lane = tid & 31;
    const int w    = tid >> 5;
    const int mw   = w >> 2;      // 0..1
    const int nw   = w & 3;       // 0..3
    const int g    = lane >> 2;   // group
    const int tig  = lane & 3;
    const int row0 = blockIdx.x * BM;

    // ---- load X tile (64 rows x 256 halves), zero-pad past N ----
    {
        uint4* xs = (uint4*)(smem + XS_OFF * 2);
        #pragma unroll
        for (int t = tid; t < BM * 32; t += 256) {
            int r = t >> 5, c = t & 31;
            uint4 v = make_uint4(0u, 0u, 0u, 0u);
            if (row0 + r < NN) v = xbf[(size_t)(row0 + r) * 32 + c];
            xs[r * 33 + c] = v;
        }
    }
    if (tid < BM) den[tid] = 0.0f;

    // precomputed ldmatrix address components
    const int lhi = (lane >> 4) << 3;            // 0 or 8
    const int lmid = ((lane >> 3) & 1) << 3;     // 0 or 8
    // GEMM1 A: row = mw*32 + tm*16 + (lane&15), col = kk + lhi   (Xs)
    const int a1row = mw * 32 + (lane & 15);
    // GEMM1 B: row = nw*32 + tp*16 + (lane&7) + lhi, col = kk + lmid  (Ms)
    const int b1row = nw * 32 + (lane & 7) + lhi;
    // GEMM2 A: row = mw*32 + tm*16 + (lane&15), col = kk + lhi   (P)
    // GEMM2 B(trans): row = kk + (lane&7) + lmid, col = nw*64 + dp*16 + lhi  (Ms)
    const int b2r = (lane & 7) + lmid;
    const int b2c = nw * 64 + lhi;

    float racc[2][8][4];
    #pragma unroll
    for (int a = 0; a < 2; a++)
        #pragma unroll
        for (int b = 0; b < 8; b++)
            #pragma unroll
            for (int c = 0; c < 4; c++) racc[a][b][c] = 0.f;

    for (int kt = 0; kt < KK / BK; kt++) {
        // ---- load M tile (128 rows x 256 halves) ----
        {
            uint4* ms = (uint4*)(smem + MS_OFF * 2);
            const uint4* src = mbf + (size_t)(kt * BK) * 32;
            #pragma unroll
            for (int t = tid; t < BK * 32; t += 256) {
                int r = t >> 5, c = t & 31;
                ms[r * 33 + c] = src[r * 32 + c];
            }
        }
        __syncthreads();

        // ---- GEMM1: S[64][128] = X . M^T ----
        float sacc[2][4][4];
        #pragma unroll
        for (int a = 0; a < 2; a++)
            #pragma unroll
            for (int b = 0; b < 4; b++)
                #pragma unroll
                for (int c = 0; c < 4; c++) sacc[a][b][c] = 0.f;

        #pragma unroll 4
        for (int kk = 0; kk < DDIM; kk += 16) {
            uint32_t af[2][4];
            #pragma unroll
            for (int tm = 0; tm < 2; tm++)
                ldsm_x4(af[tm], sbase + (uint32_t)((XS_OFF + (a1row + tm * 16) * XS_STRIDE + kk + lhi) * 2));
            #pragma unroll
            for (int tp = 0; tp < 2; tp++) {
                uint32_t bf[4];
                ldsm_x4(bf, sbase + (uint32_t)((MS_OFF + (b1row + tp * 16) * MS_STRIDE + kk + lmid) * 2));
                mma_bf16(sacc[0][2 * tp],     af[0], bf[0], bf[1]);
                mma_bf16(sacc[0][2 * tp + 1], af[0], bf[2], bf[3]);
                mma_bf16(sacc[1][2 * tp],     af[1], bf[0], bf[1]);
                mma_bf16(sacc[1][2 * tp + 1], af[1], bf[2], bf[3]);
            }
        }

        // ---- exp, row sums, pack bf16 P ----
        uint32_t* pw = (uint32_t*)smem;   // word-indexed shared
        #pragma unroll
        for (int tm = 0; tm < 2; tm++) {
            int rowA = mw * 32 + tm * 16 + g;
            int rowB = rowA + 8;
            float sA = 0.f, sB = 0.f;
            #pragma unroll
            for (int tn = 0; tn < 4; tn++) {
                float e0 = __expf(sacc[tm][tn][0]);
                float e1 = __expf(sacc[tm][tn][1]);
                float e2 = __expf(sacc[tm][tn][2]);
                float e3 = __expf(sacc[tm][tn][3]);
                sA += e0 + e1;
                sB += e2 + e3;
                uint32_t p01, p23;
                asm("cvt.rn.bf16x2.f32 %0, %1, %2;" : "=r"(p01) : "f"(e1), "f"(e0));
                asm("cvt.rn.bf16x2.f32 %0, %1, %2;" : "=r"(p23) : "f"(e3), "f"(e2));
                int n = nw * 32 + tn * 8 + 2 * tig;
                pw[(PS_OFF + rowA * PS_STRIDE + n) >> 1] = p01;
                pw[(PS_OFF + rowB * PS_STRIDE + n) >> 1] = p23;
            }
            atomicAdd(&den[rowA], sA);
            atomicAdd(&den[rowB], sB);
        }
        __syncthreads();

        // ---- GEMM2: R[64][256] += P[64][128] . M[128][256] ----
        #pragma unroll 4
        for (int kk = 0; kk < BK; kk += 16) {
            uint32_t af[2][4];
            #pragma unroll
            for (int tm = 0; tm < 2; tm++)
                ldsm_x4(af[tm], sbase + (uint32_t)((PS_OFF + (a1row + tm * 16) * PS_STRIDE + kk + lhi) * 2));
            #pragma unroll
            for (int dp = 0; dp < 4; dp++) {
                uint32_t bf[4];
                ldsm_x4_t(bf, sbase + (uint32_t)((MS_OFF + (kk + b2r) * MS_STRIDE + b2c + dp * 16) * 2));
                mma_bf16(racc[0][2 * dp],     af[0], bf[0], bf[1]);
                mma_bf16(racc[0][2 * dp + 1], af[0], bf[2], bf[3]);
                mma_bf16(racc[1][2 * dp],     af[1], bf[0], bf[1]);
                mma_bf16(racc[1][2 * dp + 1], af[1], bf[2], bf[3]);
            }
        }
        __syncthreads();
    }

    // ---- divide by denominator and store ----
    #pragma unroll
    for (int tm = 0; tm < 2; tm++) {
        int rA = mw * 32 + tm * 16 + g;
        int rB = rA + 8;
        int gA = row0 + rA, gB = row0 + rB;
        float invA = 1.0f / den[rA];
        float invB = 1.0f / den[rB];
        #pragma unroll
        for (int tn = 0; tn < 8; tn++) {
            int d2 = nw * 32 + tn * 4 + tig;   // float2 index within row
            if (gA < NN) {
                float2 v;
                v.x = racc[tm][tn][0] * invA;
                v.y = racc[tm][tn][1] * invA;
                ret2[(size_t)gA * 128 + d2] = v;
            }
            if (gB < NN) {
                float2 v;
                v.x = racc[tm][tn][2] * invB;
                v.y = racc[tm][tn][3] * invB;
                ret2[(size_t)gB * 128 + d2] = v;
            }
        }
    }
}

// ---------------- Laplacian scatter ----------------
__global__ __launch_bounds__(256)
void scatter_kernel(const float4* __restrict__ x4) {
    int gtid = blockIdx.x * blockDim.x + threadIdx.x;
    int warp = gtid >> 5;
    int lane = threadIdx.x & 31;
    if (warp >= EE) return;
    int r = g_rowi[warp];
    int c = g_coli[warp];
    float s = g_dinv[c];
    const float4* src = x4 + (size_t)c * D4;
    float4* dst = ((float4*)g_agg) + (size_t)r * D4;
    #pragma unroll
    for (int j = 0; j < 2; j++) {
        int idx = lane + 32 * j;
        float4 v = src[idx];
        v.x *= s; v.y *= s; v.z *= s; v.w *= s;
        asm volatile("red.global.v4.f32.add [%0], {%1, %2, %3, %4};"
                     :: "l"(dst + idx), "f"(v.x), "f"(v.y), "f"(v.z), "f"(v.w)
                     : "memory");
    }
}

// ---------------- combine + layernorm ----------------
__global__ __launch_bounds__(256)
void combine_ln_kernel(const float4* __restrict__ xin4,
                       const float4* __restrict__ gamma4,
                       const float4* __restrict__ beta4,
                       float4* __restrict__ out4) {
    int gtid = blockIdx.x * blockDim.x + threadIdx.x;
    int node = gtid >> 5;
    int lane = threadIdx.x & 31;
    if (node >= NN) return;

    const float lc = 2.0f * LAMBDA_C;
    const float cx = (1.0f - ALPHA_C) - ALPHA_C * lc;
    const float cr = ALPHA_C;
    const float ca = ALPHA_C * lc;

    size_t base = (size_t)node * D4;
    float s = g_dinv[node] * ca;
    const float4* rp = ((const float4*)g_ret) + base;
    const float4* ap = ((const float4*)g_agg) + base;

    float4 h[2];
    float sum = 0.f, sumsq = 0.f;
    #pragma unroll
    for (int j = 0; j < 2; j++) {
        int idx = lane + 32 * j;
        float4 xv = xin4[base + idx];
        float4 rv = rp[idx];
        float4 av = ap[idx];
        float4 hv;
        hv.x = cx * xv.x + cr * rv.x + s * av.x;
        hv.y = cx * xv.y + cr * rv.y + s * av.y;
        hv.z = cx * xv.z + cr * rv.z + s * av.z;
        hv.w = cx * xv.w + cr * rv.w + s * av.w;
        h[j] = hv;
        sum   += hv.x + hv.y + hv.z + hv.w;
        sumsq += hv.x * hv.x + hv.y * hv.y + hv.z * hv.z + hv.w * hv.w;
    }
    #pragma unroll
    for (int o = 16; o > 0; o >>= 1) {
        sum   += __shfl_xor_sync(0xffffffffu, sum, o);
        sumsq += __shfl_xor_sync(0xffffffffu, sumsq, o);
    }
    const float invD = 1.0f / (float)DDIM;
    float mu  = sum * invD;
    float var = sumsq * invD - mu * mu;
    float rs  = rsqrtf(var + EPS_C);

    #pragma unroll
    for (int j = 0; j < 2; j++) {
        int idx = lane + 32 * j;
        float4 gv = gamma4[idx];
        float4 bv = beta4[idx];
        float4 hv = h[j];
        float4 ov;
        ov.x = (hv.x - mu) * rs * gv.x + bv.x;
        ov.y = (hv.y - mu) * rs * gv.y + bv.y;
        ov.z = (hv.z - mu) * rs * gv.z + bv.z;
        ov.w = (hv.w - mu) * rs * gv.w + bv.w;
        out4[base + idx] = ov;
    }
}

// ---------------- launch ----------------
extern "C" void kernel_launch(void* const* d_in, const int* in_sizes, int n_in,
                              void* d_out, int out_size) {
    const float* x     = (const float*)d_in[0];
    const void*  eidx  = d_in[1];
    const float* mem   = (const float*)d_in[2];
    const float* gamma = (const float*)d_in[3];
    const float* beta  = (const float*)d_in[4];
    float* out = (float*)d_out;

    cudaFuncSetAttribute(hopfield_mma_kernel,
                         cudaFuncAttributeMaxDynamicSharedMemorySize, SMEM_BYTES);

    void *p_x = nullptr, *p_ret = nullptr, *p_xbf = nullptr, *p_mbf = nullptr;
    cudaGetSymbolAddress(&p_x, g_x);
    cudaGetSymbolAddress(&p_ret, g_ret);
    cudaGetSymbolAddress(&p_xbf, g_xbf);
    cudaGetSymbolAddress(&p_mbf, g_mbf);

    // graph preprocessing
    detect_kernel<<<1, 32>>>((const long long*)eidx);
    zero_deg_kernel<<<(NN + 255) / 256, 256>>>();
    convert_deg_kernel<<<(EE + 255) / 256, 256>>>(eidx);
    dinv_kernel<<<(NN + 255) / 256, 256>>>();

    // convert memory to bf16 (once)
    {
        int n16 = KK * DDIM / 8;
        conv_bf16_kernel<<<(n16 + 255) / 256, 256>>>((const float4*)mem,
                                                     (uint4*)p_mbf, n16);
    }

    const int HB = (NN + BM - 1) / BM;
    const float* xin = x;
    for (int it = 0; it < 2; it++) {
        float* xout = (it == 0) ? (float*)p_x : out;

        // convert current x to bf16
        {
            int n16 = NN * DDIM / 8;
            conv_bf16_kernel<<<(n16 + 255) / 256, 256>>>((const float4*)xin,
                                                         (uint4*)p_xbf, n16);
        }
        zero_agg_kernel<<<(NN * D4 + 255) / 256, 256>>>();
        hopfield_mma_kernel<<<HB, 256, SMEM_BYTES>>>(
            (const uint4*)p_xbf, (const uint4*)p_mbf, (float2*)p_ret);
        scatter_kernel<<<(EE * 32 + 255) / 256, 256>>>((const float4*)xin);
        combine_ln_kernel<<<(NN * 32 + 255) / 256, 256>>>(
            (const float4*)xin, (const float4*)gamma, (const float4*)beta,
            (float4*)xout);

        xin = xout;
    }
}

// round 3
// speedup vs baseline: 5.0718x; 1.7987x over previous
#include <cuda_runtime.h>
#include <cstdint>

#define NN   100000
#define EE   3200000
#define DDIM 256
#define D4   64
#define KK   1024
#define NBLK ((NN + 255) / 256)
#define ALPHA_C  0.5f
#define LAMBDA_C 0.1f
#define EPS_C    1e-5f

// hopfield mma tiling
#define BM   64
#define BK   128
#define XS_STRIDE 264
#define MS_STRIDE 264
#define PS_STRIDE 136
#define XS_OFF 0
#define MS_OFF (BM * XS_STRIDE)
#define PS_OFF (MS_OFF + BK * MS_STRIDE)
#define DEN_BYTE_OFF ((PS_OFF + BM * PS_STRIDE) * 2)
#define SMEM_BYTES (DEN_BYTE_OFF + BM * 4)

// ---------------- scratch ----------------
__device__ float g_x[(size_t)NN * DDIM];
__device__ float g_ret[(size_t)NN * DDIM];
__device__ float g_deg[NN];
__device__ float g_dinv[NN];
__device__ int   g_rowi[EE];
__device__ int   g_coli[EE];
__device__ int   g_is64;
__device__ int   g_rdeg[NN];     // out-degree per row (for CSR)
__device__ int   g_rowptr[NN];
__device__ int   g_cursor[NN];
__device__ int   g_nbr[EE];      // col indices grouped by row
__device__ int   g_pscan[NN];
__device__ int   g_bsum[NBLK];
__device__ int   g_boff[NBLK];
__device__ __align__(16) unsigned short g_xbf[(size_t)NN * DDIM];
__device__ __align__(16) unsigned short g_mbf[(size_t)KK * DDIM];

// ---------------- preprocessing ----------------
__global__ void detect_kernel(const long long* __restrict__ e64) {
    if (threadIdx.x == 0) {
        int is64 = 1;
        #pragma unroll 1
        for (int i = 0; i < 64; i++) {
            long long v = e64[i];
            if (v < 0 || v >= (long long)NN) { is64 = 0; break; }
        }
        g_is64 = is64;
    }
}

__global__ void zero_kernel() {
    int i = blockIdx.x * blockDim.x + threadIdx.x;
    if (i < NN) { g_deg[i] = 0.0f; g_rdeg[i] = 0; }
}

__global__ void convert_deg_kernel(const void* __restrict__ eidx) {
    int e = blockIdx.x * blockDim.x + threadIdx.x;
    if (e >= EE) return;
    int r, c;
    if (g_is64) {
        const long long* p = (const long long*)eidx;
        r = (int)p[e];
        c = (int)p[(size_t)EE + e];
    } else {
        const int* p = (const int*)eidx;
        r = p[e];
        c = p[EE + e];
    }
    g_rowi[e] = r;
    g_coli[e] = c;
    atomicAdd(&g_deg[c], 1.0f);
    atomicAdd(&g_rdeg[r], 1);
}

__global__ void dinv_kernel() {
    int n = blockIdx.x * blockDim.x + threadIdx.x;
    if (n >= NN) return;
    float d = g_deg[n];
    g_dinv[n] = (d > 0.0f) ? rsqrtf(fmaxf(d, 1.0f)) : 0.0f;
}

// ---- 3-kernel exclusive scan of g_rdeg -> g_rowptr / g_cursor ----
__global__ void scan1_kernel() {
    __shared__ int wsum[8];
    int i = blockIdx.x * 256 + threadIdx.x;
    int lane = threadIdx.x & 31, wid = threadIdx.x >> 5;
    int v = (i < NN) ? g_rdeg[i] : 0;
    int s = v;
    #pragma unroll
    for (int o = 1; o < 32; o <<= 1) {
        int t = __shfl_up_sync(~0u, s, o);
        if (lane >= o) s += t;
    }
    if (lane == 31) wsum[wid] = s;
    __syncthreads();
    if (wid == 0) {
        int t = (lane < 8) ? wsum[lane] : 0;
        #pragma unroll
        for (int o = 1; o < 8; o <<= 1) {
            int u = __shfl_up_sync(~0u, t, o);
            if (lane >= o) t += u;
        }
        if (lane < 8) wsum[lane] = t;
    }
    __syncthreads();
    s += (wid > 0) ? wsum[wid - 1] : 0;
    if (i < NN) g_pscan[i] = s;
    if (threadIdx.x == 255) g_bsum[blockIdx.x] = s;
}

__global__ void scan2_kernel() {
    __shared__ int sh[NBLK];
    int t = threadIdx.x;
    if (t < NBLK) sh[t] = g_bsum[t];
    __syncthreads();
    for (int o = 1; o < NBLK; o <<= 1) {
        int v = 0;
        if (t < NBLK && t >= o) v = sh[t - o];
        __syncthreads();
        if (t < NBLK) sh[t] += v;
        __syncthreads();
    }
    if (t < NBLK) g_boff[t] = (t > 0) ? sh[t - 1] : 0;
}

__global__ void scan3_kernel() {
    int i = blockIdx.x * 256 + threadIdx.x;
    if (i >= NN) return;
    int rp = g_pscan[i] - g_rdeg[i] + g_boff[blockIdx.x];
    g_rowptr[i] = rp;
    g_cursor[i] = rp;
}

__global__ void fill_kernel() {
    int e = blockIdx.x * blockDim.x + threadIdx.x;
    if (e >= EE) return;
    int pos = atomicAdd(&g_cursor[g_rowi[e]], 1);
    g_nbr[pos] = g_coli[e];
}

// fp32 -> bf16 convert
__global__ void conv_bf16_kernel(const float4* __restrict__ src,
                                 uint4* __restrict__ dst, int n16) {
    int i = blockIdx.x * blockDim.x + threadIdx.x;
    if (i >= n16) return;
    float4 a = src[2 * i], b = src[2 * i + 1];
    uint4 o;
    asm("cvt.rn.bf16x2.f32 %0, %1, %2;" : "=r"(o.x) : "f"(a.y), "f"(a.x));
    asm("cvt.rn.bf16x2.f32 %0, %1, %2;" : "=r"(o.y) : "f"(a.w), "f"(a.z));
    asm("cvt.rn.bf16x2.f32 %0, %1, %2;" : "=r"(o.z) : "f"(b.y), "f"(b.x));
    asm("cvt.rn.bf16x2.f32 %0, %1, %2;" : "=r"(o.w) : "f"(b.w), "f"(b.z));
    dst[i] = o;
}

// ---------------- mma helpers ----------------
__device__ __forceinline__ void ldsm_x4(uint32_t (&r)[4], uint32_t addr) {
    asm volatile("ldmatrix.sync.aligned.m8n8.x4.shared.b16 {%0,%1,%2,%3}, [%4];"
        : "=r"(r[0]), "=r"(r[1]), "=r"(r[2]), "=r"(r[3]) : "r"(addr));
}
__device__ __forceinline__ void ldsm_x4_t(uint32_t (&r)[4], uint32_t addr) {
    asm volatile("ldmatrix.sync.aligned.m8n8.x4.trans.shared.b16 {%0,%1,%2,%3}, [%4];"
        : "=r"(r[0]), "=r"(r[1]), "=r"(r[2]), "=r"(r[3]) : "r"(addr));
}
__device__ __forceinline__ void mma_bf16(float (&d)[4], const uint32_t (&a)[4],
                                         uint32_t b0, uint32_t b1) {
    asm volatile("mma.sync.aligned.m16n8k16.row.col.f32.bf16.bf16.f32 "
        "{%0,%1,%2,%3}, {%4,%5,%6,%7}, {%8,%9}, {%0,%1,%2,%3};"
        : "+f"(d[0]), "+f"(d[1]), "+f"(d[2]), "+f"(d[3])
        : "r"(a[0]), "r"(a[1]), "r"(a[2]), "r"(a[3]), "r"(b0), "r"(b1));
}

// ---------------- fused Hopfield via tensor cores ----------------
__global__ __launch_bounds__(256, 1)
void hopfield_mma_kernel(const uint4* __restrict__ xbf,
                         const uint4* __restrict__ mbf,
                         float2* __restrict__ ret2) {
    extern __shared__ char smem[];
    float* den = (float*)(smem + DEN_BYTE_OFF);
    uint32_t sbase = (uint32_t)__cvta_generic_to_shared(smem);

    const int tid  = threadIdx.x;
    const int lane = tid & 31;
    const int w    = tid >> 5;
    const int mw   = w >> 2;
    const int nw   = w & 3;
    const int g    = lane >> 2;
    const int tig  = lane & 3;
    const int row0 = blockIdx.x * BM;

    {
        uint4* xs = (uint4*)(smem + XS_OFF * 2);
        #pragma unroll
        for (int t = tid; t < BM * 32; t += 256) {
            int r = t >> 5, c = t & 31;
            uint4 v = make_uint4(0u, 0u, 0u, 0u);
            if (row0 + r < NN) v = xbf[(size_t)(row0 + r) * 32 + c];
            xs[r * 33 + c] = v;
        }
    }
    if (tid < BM) den[tid] = 0.0f;

    const int lhi = (lane >> 4) << 3;
    const int lmid = ((lane >> 3) & 1) << 3;
    const int a1row = mw * 32 + (lane & 15);
    const int b1row = nw * 32 + (lane & 7) + lhi;
    const int b2r = (lane & 7) + lmid;
    const int b2c = nw * 64 + lhi;

    float racc[2][8][4];
    #pragma unroll
    for (int a = 0; a < 2; a++)
        #pragma unroll
        for (int b = 0; b < 8; b++)
            #pragma unroll
            for (int c = 0; c < 4; c++) racc[a][b][c] = 0.f;

    for (int kt = 0; kt < KK / BK; kt++) {
        {
            uint4* ms = (uint4*)(smem + MS_OFF * 2);
            const uint4* src = mbf + (size_t)(kt * BK) * 32;
            #pragma unroll
            for (int t = tid; t < BK * 32; t += 256) {
                int r = t >> 5, c = t & 31;
                ms[r * 33 + c] = src[r * 32 + c];
            }
        }
        __syncthreads();

        float sacc[2][4][4];
        #pragma unroll
        for (int a = 0; a < 2; a++)
            #pragma unroll
            for (int b = 0; b < 4; b++)
                #pragma unroll
                for (int c = 0; c < 4; c++) sacc[a][b][c] = 0.f;

        #pragma unroll 4
        for (int kk = 0; kk < DDIM; kk += 16) {
            uint32_t af[2][4];
            #pragma unroll
            for (int tm = 0; tm < 2; tm++)
                ldsm_x4(af[tm], sbase + (uint32_t)((XS_OFF + (a1row + tm * 16) * XS_STRIDE + kk + lhi) * 2));
            #pragma unroll
            for (int tp = 0; tp < 2; tp++) {
                uint32_t bf[4];
                ldsm_x4(bf, sbase + (uint32_t)((MS_OFF + (b1row + tp * 16) * MS_STRIDE + kk + lmid) * 2));
                mma_bf16(sacc[0][2 * tp],     af[0], bf[0], bf[1]);
                mma_bf16(sacc[0][2 * tp + 1], af[0], bf[2], bf[3]);
                mma_bf16(sacc[1][2 * tp],     af[1], bf[0], bf[1]);
                mma_bf16(sacc[1][2 * tp + 1], af[1], bf[2], bf[3]);
            }
        }

        uint32_t* pw = (uint32_t*)smem;
        #pragma unroll
        for (int tm = 0; tm < 2; tm++) {
            int rowA = mw * 32 + tm * 16 + g;
            int rowB = rowA + 8;
            float sA = 0.f, sB = 0.f;
            #pragma unroll
            for (int tn = 0; tn < 4; tn++) {
                float e0 = __expf(sacc[tm][tn][0]);
                float e1 = __expf(sacc[tm][tn][1]);
                float e2 = __expf(sacc[tm][tn][2]);
                float e3 = __expf(sacc[tm][tn][3]);
                sA += e0 + e1;
                sB += e2 + e3;
                uint32_t p01, p23;
                asm("cvt.rn.bf16x2.f32 %0, %1, %2;" : "=r"(p01) : "f"(e1), "f"(e0));
                asm("cvt.rn.bf16x2.f32 %0, %1, %2;" : "=r"(p23) : "f"(e3), "f"(e2));
                int n = nw * 32 + tn * 8 + 2 * tig;
                pw[(PS_OFF + rowA * PS_STRIDE + n) >> 1] = p01;
                pw[(PS_OFF + rowB * PS_STRIDE + n) >> 1] = p23;
            }
            atomicAdd(&den[rowA], sA);
            atomicAdd(&den[rowB], sB);
        }
        __syncthreads();

        #pragma unroll 4
        for (int kk = 0; kk < BK; kk += 16) {
            uint32_t af[2][4];
            #pragma unroll
            for (int tm = 0; tm < 2; tm++)
                ldsm_x4(af[tm], sbase + (uint32_t)((PS_OFF + (a1row + tm * 16) * PS_STRIDE + kk + lhi) * 2));
            #pragma unroll
            for (int dp = 0; dp < 4; dp++) {
                uint32_t bf[4];
                ldsm_x4_t(bf, sbase + (uint32_t)((MS_OFF + (kk + b2r) * MS_STRIDE + b2c + dp * 16) * 2));
                mma_bf16(racc[0][2 * dp],     af[0], bf[0], bf[1]);
                mma_bf16(racc[0][2 * dp + 1], af[0], bf[2], bf[3]);
                mma_bf16(racc[1][2 * dp],     af[1], bf[0], bf[1]);
                mma_bf16(racc[1][2 * dp + 1], af[1], bf[2], bf[3]);
            }
        }
        __syncthreads();
    }

    #pragma unroll
    for (int tm = 0; tm < 2; tm++) {
        int rA = mw * 32 + tm * 16 + g;
        int rB = rA + 8;
        int gA = row0 + rA, gB = row0 + rB;
        float invA = 1.0f / den[rA];
        float invB = 1.0f / den[rB];
        #pragma unroll
        for (int tn = 0; tn < 8; tn++) {
            int d2 = nw * 32 + tn * 4 + tig;
            if (gA < NN) {
                float2 v;
                v.x = racc[tm][tn][0] * invA;
                v.y = racc[tm][tn][1] * invA;
                ret2[(size_t)gA * 128 + d2] = v;
            }
            if (gB < NN) {
                float2 v;
                v.x = racc[tm][tn][2] * invB;
                v.y = racc[tm][tn][3] * invB;
                ret2[(size_t)gB * 128 + d2] = v;
            }
        }
    }
}

// ---------------- fused gather + combine + layernorm (+bf16 out) ----------------
// one warp per node; lane owns float4 slots {lane, lane+32} of the 64-float4 row
__global__ __launch_bounds__(256)
void gather_combine_ln_kernel(const float4* __restrict__ xin4,
                              const float4* __restrict__ gamma4,
                              const float4* __restrict__ beta4,
                              float4* __restrict__ out4,
                              uint2* __restrict__ xbf2,
                              int write_bf) {
    int gtid = blockIdx.x * blockDim.x + threadIdx.x;
    int node = gtid >> 5;
    int lane = threadIdx.x & 31;
    if (node >= NN) return;

    int start = g_rowptr[node];
    int deg   = g_rdeg[node];

    float4 a0 = make_float4(0.f, 0.f, 0.f, 0.f);
    float4 a1 = make_float4(0.f, 0.f, 0.f, 0.f);

    const int* nbr = g_nbr + start;
    #pragma unroll 2
    for (int j = 0; j < deg; j++) {
        int c = __ldg(nbr + j);
        float s = __ldg(&g_dinv[c]);
        const float4* src = xin4 + (size_t)c * D4;
        float4 v0 = __ldg(src + lane);
        float4 v1 = __ldg(src + lane + 32);
        a0.x += s * v0.x; a0.y += s * v0.y; a0.z += s * v0.z; a0.w += s * v0.w;
        a1.x += s * v1.x; a1.y += s * v1.y; a1.z += s * v1.z; a1.w += s * v1.w;
    }

    const float lc = 2.0f * LAMBDA_C;
    const float cx = (1.0f - ALPHA_C) - ALPHA_C * lc;   // 0.4
    const float cr = ALPHA_C;                           // 0.5
    const float ca = ALPHA_C * lc;                      // 0.1

    size_t base = (size_t)node * D4;
    float s_n = g_dinv[node] * ca;
    const float4* rp = ((const float4*)g_ret) + base;

    float4 h[2];
    float sum = 0.f, sumsq = 0.f;
    {
        float4 xv = xin4[base + lane];
        float4 rv = rp[lane];
        float4 hv;
        hv.x = cx * xv.x + cr * rv.x + s_n * a0.x;
        hv.y = cx * xv.y + cr * rv.y + s_n * a0.y;
        hv.z = cx * xv.z + cr * rv.z + s_n * a0.z;
        hv.w = cx * xv.w + cr * rv.w + s_n * a0.w;
        h[0] = hv;
        sum   += hv.x + hv.y + hv.z + hv.w;
        sumsq += hv.x * hv.x + hv.y * hv.y + hv.z * hv.z + hv.w * hv.w;
    }
    {
        float4 xv = xin4[base + lane + 32];
        float4 rv = rp[lane + 32];
        float4 hv;
        hv.x = cx * xv.x + cr * rv.x + s_n * a1.x;
        hv.y = cx * xv.y + cr * rv.y + s_n * a1.y;
        hv.z = cx * xv.z + cr * rv.z + s_n * a1.z;
        hv.w = cx * xv.w + cr * rv.w + s_n * a1.w;
        h[1] = hv;
        sum   += hv.x + hv.y + hv.z + hv.w;
        sumsq += hv.x * hv.x + hv.y * hv.y + hv.z * hv.z + hv.w * hv.w;
    }
    #pragma unroll
    for (int o = 16; o > 0; o >>= 1) {
        sum   += __shfl_xor_sync(0xffffffffu, sum, o);
        sumsq += __shfl_xor_sync(0xffffffffu, sumsq, o);
    }
    const float invD = 1.0f / (float)DDIM;
    float mu  = sum * invD;
    float var = sumsq * invD - mu * mu;
    float rs  = rsqrtf(var + EPS_C);

    #pragma unroll
    for (int jj = 0; jj < 2; jj++) {
        int idx = lane + 32 * jj;
        float4 gv = gamma4[idx];
        float4 bv = beta4[idx];
        float4 hv = h[jj];
        float4 ov;
        ov.x = (hv.x - mu) * rs * gv.x + bv.x;
        ov.y = (hv.y - mu) * rs * gv.y + bv.y;
        ov.z = (hv.z - mu) * rs * gv.z + bv.z;
        ov.w = (hv.w - mu) * rs * gv.w + bv.w;
        out4[base + idx] = ov;
        if (write_bf) {
            uint2 pb;
            asm("cvt.rn.bf16x2.f32 %0, %1, %2;" : "=r"(pb.x) : "f"(ov.y), "f"(ov.x));
            asm("cvt.rn.bf16x2.f32 %0, %1, %2;" : "=r"(pb.y) : "f"(ov.w), "f"(ov.z));
            xbf2[base + idx] = pb;
        }
    }
}

// ---------------- launch ----------------
extern "C" void kernel_launch(void* const* d_in, const int* in_sizes, int n_in,
                              void* d_out, int out_size) {
    const float* x     = (const float*)d_in[0];
    const void*  eidx  = d_in[1];
    const float* mem   = (const float*)d_in[2];
    const float* gamma = (const float*)d_in[3];
    const float* beta  = (const float*)d_in[4];
    float* out = (float*)d_out;

    cudaFuncSetAttribute(hopfield_mma_kernel,
                         cudaFuncAttributeMaxDynamicSharedMemorySize, SMEM_BYTES);

    void *p_x = nullptr, *p_ret = nullptr, *p_xbf = nullptr, *p_mbf = nullptr;
    cudaGetSymbolAddress(&p_x, g_x);
    cudaGetSymbolAddress(&p_ret, g_ret);
    cudaGetSymbolAddress(&p_xbf, g_xbf);
    cudaGetSymbolAddress(&p_mbf, g_mbf);

    // graph preprocessing + CSR build
    detect_kernel<<<1, 32>>>((const long long*)eidx);
    zero_kernel<<<NBLK, 256>>>();
    convert_deg_kernel<<<(EE + 255) / 256, 256>>>(eidx);
    dinv_kernel<<<NBLK, 256>>>();
    scan1_kernel<<<NBLK, 256>>>();
    scan2_kernel<<<1, 512>>>();
    scan3_kernel<<<NBLK, 256>>>();
    fill_kernel<<<(EE + 255) / 256, 256>>>();

    // convert memory + initial x to bf16
    {
        int n16 = KK * DDIM / 8;
        conv_bf16_kernel<<<(n16 + 255) / 256, 256>>>((const float4*)mem,
                                                     (uint4*)p_mbf, n16);
        int m16 = NN * DDIM / 8;
        conv_bf16_kernel<<<(m16 + 255) / 256, 256>>>((const float4*)x,
                                                     (uint4*)p_xbf, m16);
    }

    const int HB = (NN + BM - 1) / BM;
    const float* xin = x;
    for (int it = 0; it < 2; it++) {
        float* xout = (it == 0) ? (float*)p_x : out;

        hopfield_mma_kernel<<<HB, 256, SMEM_BYTES>>>(
            (const uint4*)p_xbf, (const uint4*)p_mbf, (float2*)p_ret);
        gather_combine_ln_kernel<<<(NN * 32 + 255) / 256, 256>>>(
            (const float4*)xin, (const float4*)gamma, (const float4*)beta,
            (float4*)xout, (uint2*)p_xbf, (it == 0) ? 1 : 0);

        xin = xout;
    }
}

// round 4
// speedup vs baseline: 5.6773x; 1.1194x over previous
#include <cuda_runtime.h>
#include <cstdint>

#define NN   100000
#define EE   3200000
#define DDIM 256
#define D4   64
#define KK   1024
#define NBLK ((NN + 255) / 256)
#define ALPHA_C  0.5f
#define LAMBDA_C 0.1f
#define EPS_C    1e-5f

// hopfield mma tiling
#define BM   64
#define BK   128
#define XS_STRIDE 264
#define MS_STRIDE 264
#define PS_STRIDE 136
#define XS_OFF 0
#define MS_OFF (BM * XS_STRIDE)
#define PS_OFF (MS_OFF + BK * MS_STRIDE)
#define DEN_BYTE_OFF ((PS_OFF + BM * PS_STRIDE) * 2)
#define SMEM_BYTES (DEN_BYTE_OFF + BM * 4)

// ---------------- scratch ----------------
__device__ float g_x[(size_t)NN * DDIM];
__device__ float g_ret[(size_t)NN * DDIM];
__device__ float g_agg[(size_t)NN * DDIM];
__device__ float g_deg[NN];
__device__ float g_dinv[NN];
__device__ int   g_rowi[EE];
__device__ int   g_coli[EE];
__device__ int   g_is64;
__device__ int   g_rdeg[NN];
__device__ int   g_rowptr[NN];
__device__ int   g_cursor[NN];
__device__ int   g_nbr[EE];
__device__ int   g_pscan[NN];
__device__ int   g_bsum[NBLK];
__device__ int   g_boff[NBLK];
__device__ __align__(16) unsigned short g_xbf[(size_t)NN * DDIM];
__device__ __align__(16) unsigned short g_mbf[(size_t)KK * DDIM];

// ---------------- preprocessing ----------------
__global__ void detect_kernel(const long long* __restrict__ e64) {
    if (threadIdx.x == 0) {
        int is64 = 1;
        #pragma unroll 1
        for (int i = 0; i < 64; i++) {
            long long v = e64[i];
            if (v < 0 || v >= (long long)NN) { is64 = 0; break; }
        }
        g_is64 = is64;
    }
}

__global__ void zero_kernel() {
    int i = blockIdx.x * blockDim.x + threadIdx.x;
    if (i < NN) { g_deg[i] = 0.0f; g_rdeg[i] = 0; }
}

__global__ void convert_deg_kernel(const void* __restrict__ eidx) {
    int e = blockIdx.x * blockDim.x + threadIdx.x;
    if (e >= EE) return;
    int r, c;
    if (g_is64) {
        const long long* p = (const long long*)eidx;
        r = (int)p[e];
        c = (int)p[(size_t)EE + e];
    } else {
        const int* p = (const int*)eidx;
        r = p[e];
        c = p[EE + e];
    }
    g_rowi[e] = r;
    g_coli[e] = c;
    atomicAdd(&g_deg[c], 1.0f);
    atomicAdd(&g_rdeg[r], 1);
}

__global__ void dinv_kernel() {
    int n = blockIdx.x * blockDim.x + threadIdx.x;
    if (n >= NN) return;
    float d = g_deg[n];
    g_dinv[n] = (d > 0.0f) ? rsqrtf(fmaxf(d, 1.0f)) : 0.0f;
}

__global__ void scan1_kernel() {
    __shared__ int wsum[8];
    int i = blockIdx.x * 256 + threadIdx.x;
    int lane = threadIdx.x & 31, wid = threadIdx.x >> 5;
    int v = (i < NN) ? g_rdeg[i] : 0;
    int s = v;
    #pragma unroll
    for (int o = 1; o < 32; o <<= 1) {
        int t = __shfl_up_sync(~0u, s, o);
        if (lane >= o) s += t;
    }
    if (lane == 31) wsum[wid] = s;
    __syncthreads();
    if (wid == 0) {
        int t = (lane < 8) ? wsum[lane] : 0;
        #pragma unroll
        for (int o = 1; o < 8; o <<= 1) {
            int u = __shfl_up_sync(~0u, t, o);
            if (lane >= o) t += u;
        }
        if (lane < 8) wsum[lane] = t;
    }
    __syncthreads();
    s += (wid > 0) ? wsum[wid - 1] : 0;
    if (i < NN) g_pscan[i] = s;
    if (threadIdx.x == 255) g_bsum[blockIdx.x] = s;
}

__global__ void scan2_kernel() {
    __shared__ int sh[NBLK];
    int t = threadIdx.x;
    if (t < NBLK) sh[t] = g_bsum[t];
    __syncthreads();
    for (int o = 1; o < NBLK; o <<= 1) {
        int v = 0;
        if (t < NBLK && t >= o) v = sh[t - o];
        __syncthreads();
        if (t < NBLK) sh[t] += v;
        __syncthreads();
    }
    if (t < NBLK) g_boff[t] = (t > 0) ? sh[t - 1] : 0;
}

__global__ void scan3_kernel() {
    int i = blockIdx.x * 256 + threadIdx.x;
    if (i >= NN) return;
    int rp = g_pscan[i] - g_rdeg[i] + g_boff[blockIdx.x];
    g_rowptr[i] = rp;
    g_cursor[i] = rp;
}

__global__ void fill_kernel() {
    int e = blockIdx.x * blockDim.x + threadIdx.x;
    if (e >= EE) return;
    int pos = atomicAdd(&g_cursor[g_rowi[e]], 1);
    g_nbr[pos] = g_coli[e];
}

__global__ void conv_bf16_kernel(const float4* __restrict__ src,
                                 uint4* __restrict__ dst, int n16) {
    int i = blockIdx.x * blockDim.x + threadIdx.x;
    if (i >= n16) return;
    float4 a = src[2 * i], b = src[2 * i + 1];
    uint4 o;
    asm("cvt.rn.bf16x2.f32 %0, %1, %2;" : "=r"(o.x) : "f"(a.y), "f"(a.x));
    asm("cvt.rn.bf16x2.f32 %0, %1, %2;" : "=r"(o.y) : "f"(a.w), "f"(a.z));
    asm("cvt.rn.bf16x2.f32 %0, %1, %2;" : "=r"(o.z) : "f"(b.y), "f"(b.x));
    asm("cvt.rn.bf16x2.f32 %0, %1, %2;" : "=r"(o.w) : "f"(b.w), "f"(b.z));
    dst[i] = o;
}

// ---------------- mma helpers ----------------
__device__ __forceinline__ void ldsm_x4(uint32_t (&r)[4], uint32_t addr) {
    asm volatile("ldmatrix.sync.aligned.m8n8.x4.shared.b16 {%0,%1,%2,%3}, [%4];"
        : "=r"(r[0]), "=r"(r[1]), "=r"(r[2]), "=r"(r[3]) : "r"(addr));
}
__device__ __forceinline__ void ldsm_x4_t(uint32_t (&r)[4], uint32_t addr) {
    asm volatile("ldmatrix.sync.aligned.m8n8.x4.trans.shared.b16 {%0,%1,%2,%3}, [%4];"
        : "=r"(r[0]), "=r"(r[1]), "=r"(r[2]), "=r"(r[3]) : "r"(addr));
}
__device__ __forceinline__ void mma_bf16(float (&d)[4], const uint32_t (&a)[4],
                                         uint32_t b0, uint32_t b1) {
    asm volatile("mma.sync.aligned.m16n8k16.row.col.f32.bf16.bf16.f32 "
        "{%0,%1,%2,%3}, {%4,%5,%6,%7}, {%8,%9}, {%0,%1,%2,%3};"
        : "+f"(d[0]), "+f"(d[1]), "+f"(d[2]), "+f"(d[3])
        : "r"(a[0]), "r"(a[1]), "r"(a[2]), "r"(a[3]), "r"(b0), "r"(b1));
}

// ---------------- fused Hopfield via tensor cores ----------------
__global__ __launch_bounds__(256, 1)
void hopfield_mma_kernel(const uint4* __restrict__ xbf,
                         const uint4* __restrict__ mbf,
                         float2* __restrict__ ret2) {
    extern __shared__ char smem[];
    float* den = (float*)(smem + DEN_BYTE_OFF);
    uint32_t sbase = (uint32_t)__cvta_generic_to_shared(smem);

    const int tid  = threadIdx.x;
    const int lane = tid & 31;
    const int w    = tid >> 5;
    const int mw   = w >> 2;
    const int nw   = w & 3;
    const int g    = lane >> 2;
    const int tig  = lane & 3;
    const int row0 = blockIdx.x * BM;

    {
        uint4* xs = (uint4*)(smem + XS_OFF * 2);
        #pragma unroll
        for (int t = tid; t < BM * 32; t += 256) {
            int r = t >> 5, c = t & 31;
            uint4 v = make_uint4(0u, 0u, 0u, 0u);
            if (row0 + r < NN) v = xbf[(size_t)(row0 + r) * 32 + c];
            xs[r * 33 + c] = v;
        }
    }
    if (tid < BM) den[tid] = 0.0f;

    const int lhi = (lane >> 4) << 3;
    const int lmid = ((lane >> 3) & 1) << 3;
    const int a1row = mw * 32 + (lane & 15);
    const int b1row = nw * 32 + (lane & 7) + lhi;
    const int b2r = (lane & 7) + lmid;
    const int b2c = nw * 64 + lhi;

    float racc[2][8][4];
    #pragma unroll
    for (int a = 0; a < 2; a++)
        #pragma unroll
        for (int b = 0; b < 8; b++)
            #pragma unroll
            for (int c = 0; c < 4; c++) racc[a][b][c] = 0.f;

    for (int kt = 0; kt < KK / BK; kt++) {
        {
            uint4* ms = (uint4*)(smem + MS_OFF * 2);
            const uint4* src = mbf + (size_t)(kt * BK) * 32;
            #pragma unroll
            for (int t = tid; t < BK * 32; t += 256) {
                int r = t >> 5, c = t & 31;
                ms[r * 33 + c] = src[r * 32 + c];
            }
        }
        __syncthreads();

        float sacc[2][4][4];
        #pragma unroll
        for (int a = 0; a < 2; a++)
            #pragma unroll
            for (int b = 0; b < 4; b++)
                #pragma unroll
                for (int c = 0; c < 4; c++) sacc[a][b][c] = 0.f;

        #pragma unroll 4
        for (int kk = 0; kk < DDIM; kk += 16) {
            uint32_t af[2][4];
            #pragma unroll
            for (int tm = 0; tm < 2; tm++)
                ldsm_x4(af[tm], sbase + (uint32_t)((XS_OFF + (a1row + tm * 16) * XS_STRIDE + kk + lhi) * 2));
            #pragma unroll
            for (int tp = 0; tp < 2; tp++) {
                uint32_t bf[4];
                ldsm_x4(bf, sbase + (uint32_t)((MS_OFF + (b1row + tp * 16) * MS_STRIDE + kk + lmid) * 2));
                mma_bf16(sacc[0][2 * tp],     af[0], bf[0], bf[1]);
                mma_bf16(sacc[0][2 * tp + 1], af[0], bf[2], bf[3]);
                mma_bf16(sacc[1][2 * tp],     af[1], bf[0], bf[1]);
                mma_bf16(sacc[1][2 * tp + 1], af[1], bf[2], bf[3]);
            }
        }

        uint32_t* pw = (uint32_t*)smem;
        #pragma unroll
        for (int tm = 0; tm < 2; tm++) {
            int rowA = mw * 32 + tm * 16 + g;
            int rowB = rowA + 8;
            float sA = 0.f, sB = 0.f;
            #pragma unroll
            for (int tn = 0; tn < 4; tn++) {
                float e0 = __expf(sacc[tm][tn][0]);
                float e1 = __expf(sacc[tm][tn][1]);
                float e2 = __expf(sacc[tm][tn][2]);
                float e3 = __expf(sacc[tm][tn][3]);
                sA += e0 + e1;
                sB += e2 + e3;
                uint32_t p01, p23;
                asm("cvt.rn.bf16x2.f32 %0, %1, %2;" : "=r"(p01) : "f"(e1), "f"(e0));
                asm("cvt.rn.bf16x2.f32 %0, %1, %2;" : "=r"(p23) : "f"(e3), "f"(e2));
                int n = nw * 32 + tn * 8 + 2 * tig;
                pw[(PS_OFF + rowA * PS_STRIDE + n) >> 1] = p01;
                pw[(PS_OFF + rowB * PS_STRIDE + n) >> 1] = p23;
            }
            atomicAdd(&den[rowA], sA);
            atomicAdd(&den[rowB], sB);
        }
        __syncthreads();

        #pragma unroll 4
        for (int kk = 0; kk < BK; kk += 16) {
            uint32_t af[2][4];
            #pragma unroll
            for (int tm = 0; tm < 2; tm++)
                ldsm_x4(af[tm], sbase + (uint32_t)((PS_OFF + (a1row + tm * 16) * PS_STRIDE + kk + lhi) * 2));
            #pragma unroll
            for (int dp = 0; dp < 4; dp++) {
                uint32_t bf[4];
                ldsm_x4_t(bf, sbase + (uint32_t)((MS_OFF + (kk + b2r) * MS_STRIDE + b2c + dp * 16) * 2));
                mma_bf16(racc[0][2 * dp],     af[0], bf[0], bf[1]);
                mma_bf16(racc[0][2 * dp + 1], af[0], bf[2], bf[3]);
                mma_bf16(racc[1][2 * dp],     af[1], bf[0], bf[1]);
                mma_bf16(racc[1][2 * dp + 1], af[1], bf[2], bf[3]);
            }
        }
        __syncthreads();
    }

    #pragma unroll
    for (int tm = 0; tm < 2; tm++) {
        int rA = mw * 32 + tm * 16 + g;
        int rB = rA + 8;
        int gA = row0 + rA, gB = row0 + rB;
        float invA = 1.0f / den[rA];
        float invB = 1.0f / den[rB];
        #pragma unroll
        for (int tn = 0; tn < 8; tn++) {
            int d2 = nw * 32 + tn * 4 + tig;
            if (gA < NN) {
                float2 v;
                v.x = racc[tm][tn][0] * invA;
                v.y = racc[tm][tn][1] * invA;
                ret2[(size_t)gA * 128 + d2] = v;
            }
            if (gB < NN) {
                float2 v;
                v.x = racc[tm][tn][2] * invB;
                v.y = racc[tm][tn][3] * invB;
                ret2[(size_t)gB * 128 + d2] = v;
            }
        }
    }
}

// ---------------- bf16 gather: agg[row] = sum dinv[c] * xbf[c] ----------------
// one warp per node; lane owns uint4 slot lane (8 bf16 = d-values 8*lane..8*lane+7)
__device__ __forceinline__ float bflo(uint32_t w) { return __uint_as_float(w << 16); }
__device__ __forceinline__ float bfhi(uint32_t w) { return __uint_as_float(w & 0xffff0000u); }

__global__ __launch_bounds__(256)
void gather_kernel() {
    int gtid = blockIdx.x * blockDim.x + threadIdx.x;
    int node = gtid >> 5;
    int lane = threadIdx.x & 31;
    if (node >= NN) return;

    int start = g_rowptr[node];
    int deg   = g_rdeg[node];
    const uint4* xbf4 = (const uint4*)g_xbf;

    float a[8];
    #pragma unroll
    for (int k = 0; k < 8; k++) a[k] = 0.f;

    for (int base = 0; base < deg; base += 32) {
        int idx = base + lane;
        int c_l = 0;
        float s_l = 0.f;
        if (idx < deg) {
            c_l = __ldg(g_nbr + start + idx);
            s_l = __ldg(g_dinv + c_l);
        }
        int cnt = min(32, deg - base);
        #pragma unroll 4
        for (int jj = 0; jj < cnt; jj++) {
            int   c = __shfl_sync(~0u, c_l, jj);
            float s = __shfl_sync(~0u, s_l, jj);
            uint4 v = __ldg(xbf4 + (size_t)c * 32 + lane);
            a[0] += s * bflo(v.x); a[1] += s * bfhi(v.x);
            a[2] += s * bflo(v.y); a[3] += s * bfhi(v.y);
            a[4] += s * bflo(v.z); a[5] += s * bfhi(v.z);
            a[6] += s * bflo(v.w); a[7] += s * bfhi(v.w);
        }
    }

    float4* agg4 = (float4*)g_agg;
    float4 o0 = make_float4(a[0], a[1], a[2], a[3]);
    float4 o1 = make_float4(a[4], a[5], a[6], a[7]);
    agg4[(size_t)node * D4 + 2 * lane]     = o0;
    agg4[(size_t)node * D4 + 2 * lane + 1] = o1;
}

// ---------------- combine + layernorm (+bf16 out) ----------------
__global__ __launch_bounds__(256)
void combine_ln_kernel(const float4* __restrict__ xin4,
                       const float4* __restrict__ gamma4,
                       const float4* __restrict__ beta4,
                       float4* __restrict__ out4,
                       uint2* __restrict__ xbf2,
                       int write_bf) {
    int gtid = blockIdx.x * blockDim.x + threadIdx.x;
    int node = gtid >> 5;
    int lane = threadIdx.x & 31;
    if (node >= NN) return;

    const float lc = 2.0f * LAMBDA_C;
    const float cx = (1.0f - ALPHA_C) - ALPHA_C * lc;
    const float cr = ALPHA_C;
    const float ca = ALPHA_C * lc;

    size_t base = (size_t)node * D4;
    float s_n = g_dinv[node] * ca;
    const float4* rp = ((const float4*)g_ret) + base;
    const float4* ap = ((const float4*)g_agg) + base;

    float4 h[2];
    float sum = 0.f, sumsq = 0.f;
    #pragma unroll
    for (int j = 0; j < 2; j++) {
        int idx = lane + 32 * j;
        float4 xv = xin4[base + idx];
        float4 rv = rp[idx];
        float4 av = ap[idx];
        float4 hv;
        hv.x = cx * xv.x + cr * rv.x + s_n * av.x;
        hv.y = cx * xv.y + cr * rv.y + s_n * av.y;
        hv.z = cx * xv.z + cr * rv.z + s_n * av.z;
        hv.w = cx * xv.w + cr * rv.w + s_n * av.w;
        h[j] = hv;
        sum   += hv.x + hv.y + hv.z + hv.w;
        sumsq += hv.x * hv.x + hv.y * hv.y + hv.z * hv.z + hv.w * hv.w;
    }
    #pragma unroll
    for (int o = 16; o > 0; o >>= 1) {
        sum   += __shfl_xor_sync(0xffffffffu, sum, o);
        sumsq += __shfl_xor_sync(0xffffffffu, sumsq, o);
    }
    const float invD = 1.0f / (float)DDIM;
    float mu  = sum * invD;
    float var = sumsq * invD - mu * mu;
    float rs  = rsqrtf(var + EPS_C);

    #pragma unroll
    for (int jj = 0; jj < 2; jj++) {
        int idx = lane + 32 * jj;
        float4 gv = gamma4[idx];
        float4 bv = beta4[idx];
        float4 hv = h[jj];
        float4 ov;
        ov.x = (hv.x - mu) * rs * gv.x + bv.x;
        ov.y = (hv.y - mu) * rs * gv.y + bv.y;
        ov.z = (hv.z - mu) * rs * gv.z + bv.z;
        ov.w = (hv.w - mu) * rs * gv.w + bv.w;
        out4[base + idx] = ov;
        if (write_bf) {
            uint2 pb;
            asm("cvt.rn.bf16x2.f32 %0, %1, %2;" : "=r"(pb.x) : "f"(ov.y), "f"(ov.x));
            asm("cvt.rn.bf16x2.f32 %0, %1, %2;" : "=r"(pb.y) : "f"(ov.w), "f"(ov.z));
            xbf2[base + idx] = pb;
        }
    }
}

// ---------------- launch ----------------
extern "C" void kernel_launch(void* const* d_in, const int* in_sizes, int n_in,
                              void* d_out, int out_size) {
    const float* x     = (const float*)d_in[0];
    const void*  eidx  = d_in[1];
    const float* mem   = (const float*)d_in[2];
    const float* gamma = (const float*)d_in[3];
    const float* beta  = (const float*)d_in[4];
    float* out = (float*)d_out;

    cudaFuncSetAttribute(hopfield_mma_kernel,
                         cudaFuncAttributeMaxDynamicSharedMemorySize, SMEM_BYTES);

    void *p_x = nullptr, *p_ret = nullptr, *p_xbf = nullptr, *p_mbf = nullptr;
    cudaGetSymbolAddress(&p_x, g_x);
    cudaGetSymbolAddress(&p_ret, g_ret);
    cudaGetSymbolAddress(&p_xbf, g_xbf);
    cudaGetSymbolAddress(&p_mbf, g_mbf);

    // side stream + events for gather/hopfield overlap (created once, outside capture)
    static cudaStream_t s2 = nullptr;
    static cudaEvent_t evF = nullptr, evJ = nullptr;
    if (s2 == nullptr) {
        cudaStreamCreateWithFlags(&s2, cudaStreamNonBlocking);
        cudaEventCreateWithFlags(&evF, cudaEventDisableTiming);
        cudaEventCreateWithFlags(&evJ, cudaEventDisableTiming);
    }

    // graph preprocessing + CSR build
    detect_kernel<<<1, 32>>>((const long long*)eidx);
    zero_kernel<<<NBLK, 256>>>();
    convert_deg_kernel<<<(EE + 255) / 256, 256>>>(eidx);
    dinv_kernel<<<NBLK, 256>>>();
    scan1_kernel<<<NBLK, 256>>>();
    scan2_kernel<<<1, 512>>>();
    scan3_kernel<<<NBLK, 256>>>();
    fill_kernel<<<(EE + 255) / 256, 256>>>();

    // convert memory + initial x to bf16
    {
        int n16 = KK * DDIM / 8;
        conv_bf16_kernel<<<(n16 + 255) / 256, 256>>>((const float4*)mem,
                                                     (uint4*)p_mbf, n16);
        int m16 = NN * DDIM / 8;
        conv_bf16_kernel<<<(m16 + 255) / 256, 256>>>((const float4*)x,
                                                     (uint4*)p_xbf, m16);
    }

    const int HB = (NN + BM - 1) / BM;
    const float* xin = x;
    for (int it = 0; it < 2; it++) {
        float* xout = (it == 0) ? (float*)p_x : out;

        // fork: gather on s2, hopfield on main stream (both read xbf only)
        cudaEventRecord(evF, 0);
        cudaStreamWaitEvent(s2, evF, 0);
        gather_kernel<<<(NN * 32 + 255) / 256, 256, 0, s2>>>();
        hopfield_mma_kernel<<<HB, 256, SMEM_BYTES>>>(
            (const uint4*)p_xbf, (const uint4*)p_mbf, (float2*)p_ret);
        cudaEventRecord(evJ, s2);
        cudaStreamWaitEvent(0, evJ, 0);

        combine_ln_kernel<<<(NN * 32 + 255) / 256, 256>>>(
            (const float4*)xin, (const float4*)gamma, (const float4*)beta,
            (float4*)xout, (uint2*)p_xbf, (it == 0) ? 1 : 0);

        xin = xout;
    }
}